// round 3
// baseline (speedup 1.0000x reference)
#include <cuda_runtime.h>

// Shapes fixed by the problem: bz=4, C=32, H=W=256, NF=12 focal slices.
#define NF    12
#define NFH   6               // focals per reduce block (split 2 ways)
#define BZ    4
#define C_    32
#define HW    65536           // 256*256
#define CHW   (C_ * HW)       // 2,097,152
#define CHW4  (CHW / 4)       // 524,288 = 2^19
#define HW4   (HW / 4)        // 16,384

#define BPB   256             // reduction blocks along the chunk axis
#define TPB   256
#define CHUNK (CHW4 / BPB)    // 2048 float4 per block

// Scratch (no allocation allowed).
__device__ float    g_part[BZ * NF * BPB];   // 48 KB partials
__device__ int      g_sel[2 * BZ];
__device__ unsigned g_count = 0;             // last-block counter (self-resetting)

// ---------------------------------------------------------------------------
// Kernel 1: reduce + (in the last block) final selection.
// grid = (BPB, BZ*2): blockIdx.y = b*2 + half, half picks focals [6h, 6h+6).
// ---------------------------------------------------------------------------
__global__ __launch_bounds__(TPB, 3) void k_reduce(const float* __restrict__ x,
                                                   const float* __restrict__ xf,
                                                   const float* __restrict__ sal) {
    const int b    = blockIdx.y >> 1;
    const int half = blockIdx.y & 1;
    const int f0   = half * NFH;
    const int base = blockIdx.x * CHUNK;

    const float4* __restrict__ xp = (const float4*)(x   + (size_t)b * CHW);
    const float4* __restrict__ sp = (const float4*)(sal + (size_t)b * HW);
    // slice f (global) starts at (f*BZ + b)*CHW floats; stride between f's is BZ*CHW
    const float4* __restrict__ fbase =
        (const float4*)(xf + ((size_t)f0 * BZ + b) * CHW);
    const size_t fstride4 = (size_t)BZ * CHW4;   // float4 stride between focals

    float acc[NFH];
#pragma unroll
    for (int k = 0; k < NFH; ++k) acc[k] = 0.f;

    for (int i = threadIdx.x; i < CHUNK; i += TPB) {
        const int v = base + i;
        const float4 a = xp[v];
        const float4 s = sp[v & (HW4 - 1)];       // sal broadcast over channels
        float4 g[NFH];
#pragma unroll
        for (int k = 0; k < NFH; ++k) g[k] = __ldcs(fbase + k * fstride4 + v);
#pragma unroll
        for (int k = 0; k < NFH; ++k) {
            acc[k] += fabsf(s.x * (a.x - g[k].x));
            acc[k] += fabsf(s.y * (a.y - g[k].y));
            acc[k] += fabsf(s.z * (a.z - g[k].z));
            acc[k] += fabsf(s.w * (a.w - g[k].w));
        }
    }

    // Warp shuffle reduce, then combine warps in shared.
    const int lane = threadIdx.x & 31;
    const int warp = threadIdx.x >> 5;
#pragma unroll
    for (int k = 0; k < NFH; ++k) {
        float v = acc[k];
#pragma unroll
        for (int o = 16; o > 0; o >>= 1)
            v += __shfl_down_sync(0xffffffffu, v, o);
        acc[k] = v;
    }
    __shared__ float sh[TPB / 32][NFH];
    if (lane == 0) {
#pragma unroll
        for (int k = 0; k < NFH; ++k) sh[warp][k] = acc[k];
    }
    __syncthreads();
    if (threadIdx.x < NFH) {
        const int k = threadIdx.x;
        float s = 0.f;
#pragma unroll
        for (int w = 0; w < TPB / 32; ++w) s += sh[w][k];
        g_part[(b * NF + f0 + k) * BPB + blockIdx.x] = s;
    }

    // ---- last-block-done: run selection in whichever block finishes last ----
    __shared__ bool amLast;
    if (threadIdx.x == 0) {
        __threadfence();
        const unsigned total = gridDim.x * gridDim.y;
        amLast = (atomicAdd(&g_count, 1u) == total - 1u);
    }
    __syncthreads();
    if (!amLast) return;

    // Final reduction in double, fixed order: 4 threads per (b,f), 64 each.
    __shared__ double part4[BZ * NF][4];
    __shared__ double mae[BZ * NF];
    const int t = threadIdx.x;
    if (t < BZ * NF * 4) {
        const int bf = t >> 2;
        const int g  = t & 3;
        double s = 0.0;
#pragma unroll 8
        for (int q = 0; q < BPB / 4; ++q)
            s += (double)__ldcg(&g_part[bf * BPB + g * (BPB / 4) + q]);
        part4[bf][g] = s;
    }
    __syncthreads();
    if (t < BZ * NF)
        mae[t] = ((part4[t][0] + part4[t][1]) + part4[t][2]) + part4[t][3];
    __syncthreads();
    if (t < BZ) {
        double best = -1.0;
        int bi = 0, bj = 0;
        for (int i = 0; i < NF; ++i)
            for (int j = i + 1; j < NF; ++j) {
                const double d = mae[t * NF + i] - mae[t * NF + j];
                const double v = d * d;          // 0.5 factor irrelevant for order
                if (v > best) { best = v; bi = i; bj = j; }
            }
        if (!(best > 0.0)) { bi = 0; bj = 0; }
        g_sel[t]      = bi;
        g_sel[BZ + t] = bj;
    }
    if (t == 0) g_count = 0;   // reset for next graph replay
}

// ---------------------------------------------------------------------------
// Kernel 2: gather-copy, 8 float4 per thread, streaming.
// Block chunk = TPB*8 = 2048 float4, divides CHW4 -> one slice per block.
// ---------------------------------------------------------------------------
#define CPT 8
__global__ __launch_bounds__(TPB) void k_copy(const float* __restrict__ xf,
                                              float* __restrict__ out) {
    const long long q0 = (long long)blockIdx.x * (TPB * CPT);
    const int r     = (int)(q0 >> 19);      // output row 0..7, constant per block
    const int b     = r & (BZ - 1);
    const int which = r >> 2;
    const int f     = g_sel[which * BZ + b];

    const float4* __restrict__ src = (const float4*)(xf + ((size_t)f * BZ + b) * CHW);
    float4* __restrict__ dst = (float4*)out;

#pragma unroll
    for (int c = 0; c < CPT; ++c) {
        const long long q = q0 + c * TPB + threadIdx.x;
        const int n4 = (int)(q & (CHW4 - 1));
        __stcs(&dst[q], __ldcg(&src[n4]));
    }
}

// ---------------------------------------------------------------------------
extern "C" void kernel_launch(void* const* d_in, const int* in_sizes, int n_in,
                              void* d_out, int out_size) {
    const float* x   = (const float*)d_in[0];   // [4,32,256,256]
    const float* xf  = (const float*)d_in[1];   // [48,32,256,256]
    const float* sal = (const float*)d_in[2];   // [4,1,256,256]
    float*       out = (float*)d_out;           // [8,32,256,256]

    dim3 gridR(BPB, BZ * 2);
    k_reduce<<<gridR, TPB>>>(x, xf, sal);
    const unsigned blocksC = (unsigned)((2LL * BZ * CHW4) / (TPB * CPT)); // 2048
    k_copy<<<blocksC, TPB>>>(xf, out);
}